// round 6
// baseline (speedup 1.0000x reference)
#include <cuda_runtime.h>
#include <cstdint>

// Cost volume: out[b,k,h,w] = (1/81) * sum_c x1[b,c,h,w] * x2[b,c,h-i,w-j]
//   i,j in [-4,4], k = (9i+j) mod 81. Zero padding. B=4,C=128,H=128,W=256,D=81.
//
// R5: R3 geometry (9 warps, warp g owns di=g-4; tile 4h x 64w; P=8 px/lane;
// acc[9][8]=72; best LDS ratio 3.0 FMA/float) but WITHOUT the 2-CTA register
// cap that caused R3's spills: __launch_bounds__(288,1) -> 255-reg budget,
// zero spills, 1 CTA/SM (9 warps saturate the per-SM LDS crossbar).

#define Bn 4
#define Cn 128
#define Hn 128
#define Wn 256
#define Dn 81
#define TH 4
#define TW 64
#define CC 4
#define NCH (Cn / CC)       // 32 chunks
#define S2H (TH + 8)        // 12
#define S2W (TW + 8)        // 72
#define NTHR 288

#define S1_F4 (CC * TH * TW / 4)    // 256
#define S2_F4 (CC * S2H * S2W / 4)  // 864

__device__ __forceinline__ void cp16(uint32_t saddr, const float* gptr, bool ok) {
    int sz = ok ? 16 : 0;
    asm volatile("cp.async.cg.shared.global [%0], [%1], 16, %2;\n"
                 :: "r"(saddr), "l"(gptr), "r"(sz));
}
__device__ __forceinline__ void cp_commit() {
    asm volatile("cp.async.commit_group;\n" ::: "memory");
}
template <int N>
__device__ __forceinline__ void cp_wait() {
    asm volatile("cp.async.wait_group %0;\n" :: "n"(N) : "memory");
}

__global__ __launch_bounds__(NTHR, 1)
void costvol_kernel(const float* __restrict__ x1,
                    const float* __restrict__ x2,
                    float* __restrict__ out) {
    __shared__ __align__(16) float s1[2][CC][TH][TW];   // 2 * 4 KB
    __shared__ __align__(16) float s2[2][CC][S2H][S2W]; // 2 * 13.5 KB

    const int w0 = blockIdx.x * TW;
    const int h0 = blockIdx.y * TH;
    const int b  = blockIdx.z;

    const int tid  = threadIdx.x;
    const int g    = tid >> 5;       // warp id = ii (di = g-4), 0..8
    const int lane = tid & 31;
    const int ty   = lane >> 3;      // 4 rows
    const int txl  = lane & 7;       // 8 lane-columns, 8 px each

    const float* x1b = x1 + (size_t)(b * Cn) * Hn * Wn;
    const float* x2b = x2 + (size_t)(b * Cn) * Hn * Wn;

    auto prefetch = [&](int c0, int st) {
        // s1: 256 float4 (threads 0..255)
        if (tid < S1_F4) {
            int cc  = tid >> 6;               // 64 f4 per channel
            int rem = tid & 63;
            int hh  = rem >> 4;               // 16 f4 per row
            int k4  = rem & 15;
            uint32_t sa = (uint32_t)__cvta_generic_to_shared(&s1[st][cc][hh][4 * k4]);
            cp16(sa, x1b + (((size_t)(c0 + cc) * Hn + h0 + hh) * Wn + w0 + 4 * k4), true);
        }
        // s2: 864 float4 (3 rounds of 288)
#pragma unroll
        for (int q = 0; q < 3; q++) {
            int f = tid + q * NTHR;
            if (f < S2_F4) {
                int cc  = f / (S2H * (S2W / 4));
                int rem = f - cc * (S2H * (S2W / 4));
                int row = rem / (S2W / 4);
                int k4  = rem - row * (S2W / 4);
                int hg  = h0 - 4 + row;
                int wg  = w0 - 4 + 4 * k4;
                bool ok = ((unsigned)hg < (unsigned)Hn) && ((unsigned)wg < (unsigned)Wn);
                const float* gp = ok ? (x2b + (((size_t)cc + c0) * Hn + hg) * (size_t)Wn + wg)
                                     : x2b;
                uint32_t sa = (uint32_t)__cvta_generic_to_shared(&s2[st][cc][row][4 * k4]);
                cp16(sa, gp, ok);
            }
        }
        cp_commit();
    };

    float acc[9][8];
#pragma unroll
    for (int jj = 0; jj < 9; jj++)
#pragma unroll
        for (int p = 0; p < 8; p++) acc[jj][p] = 0.f;

    prefetch(0, 0);

    for (int it = 0; it < NCH; it++) {
        const int st = it & 1;
        if (it + 1 < NCH) {
            prefetch((it + 1) * CC, st ^ 1);
            cp_wait<1>();
        } else {
            cp_wait<0>();
        }
        __syncthreads();

#pragma unroll
        for (int cc = 0; cc < CC; cc++) {
            // a: 8 consecutive x1 px for this lane (2 aligned LDS.128)
            const float4 av0 = *(const float4*)&s1[st][cc][ty][8 * txl];
            const float4 av1 = *(const float4*)&s1[st][cc][ty][8 * txl + 4];
            const float a[8] = {av0.x, av0.y, av0.z, av0.w,
                                av1.x, av1.y, av1.z, av1.w};
            // x2 window: 16 floats, row ty+8-g, starting local col 8*txl
            const float* rp = &s2[st][cc][ty + 8 - g][8 * txl];
            float wnd[16];
#pragma unroll
            for (int m = 0; m < 16; m += 4) {
                float4 t = *(const float4*)(rp + m);   // aligned LDS.128
                wnd[m] = t.x; wnd[m + 1] = t.y; wnd[m + 2] = t.z; wnd[m + 3] = t.w;
            }
#pragma unroll
            for (int jj = 0; jj < 9; jj++) {
#pragma unroll
                for (int p = 0; p < 8; p++)
                    acc[jj][p] += a[p] * wnd[p + 8 - jj];
            }
        }
        __syncthreads();
    }

    // ---- epilogue: ii = g, k = (9*g + jj + 41) mod 81 ----
    const float inv = 1.0f / 81.0f;
    const int hg = h0 + ty;
    const int wg = w0 + 8 * txl;
#pragma unroll
    for (int jj = 0; jj < 9; jj++) {
        int k = 9 * g + jj + 41;
        if (k >= 81) k -= 81;
        float* op = out + (((size_t)((b * Dn + k) * Hn + hg)) * Wn + wg);
        float4 v0 = make_float4(acc[jj][0] * inv, acc[jj][1] * inv,
                                acc[jj][2] * inv, acc[jj][3] * inv);
        float4 v1 = make_float4(acc[jj][4] * inv, acc[jj][5] * inv,
                                acc[jj][6] * inv, acc[jj][7] * inv);
        *(float4*)op = v0;
        *(float4*)(op + 4) = v1;
    }
}

extern "C" void kernel_launch(void* const* d_in, const int* in_sizes, int n_in,
                              void* d_out, int out_size) {
    (void)in_sizes; (void)n_in; (void)out_size;
    const float* x1 = (const float*)d_in[0];
    const float* x2 = (const float*)d_in[1];
    float* out = (float*)d_out;
    dim3 grid(Wn / TW, Hn / TH, Bn);   // (4, 32, 4) = 512 blocks
    costvol_kernel<<<grid, NTHR>>>(x1, x2, out);
}

// round 9
// speedup vs baseline: 1.4054x; 1.4054x over previous
#include <cuda_runtime.h>
#include <cstdint>

// Cost volume: out[b,k,h,w] = (1/81) * sum_c x1[b,c,h,w] * x2[b,c,h-i,w-j]
//   i,j in [-4,4], k = (9i+j) mod 81. Zero padding. B=4,C=128,H=128,W=256,D=81.
//
// R8 = R6/R7 (never ran; container-level failures) with the fma.rn.f32x2
// inline asm rewritten to the separate-destination "=l" form (same semantics,
// safer constraint pattern). Geometry = R2 (94.6us best): 192 thr = 3 groups
// x 64; group g owns di in {3g..3g+2}; 4h x 64w tile, P=4 px/thread; CC=4
// cp.async double buffer; launch_bounds(192,2).

#define Bn 4
#define Cn 128
#define Hn 128
#define Wn 256
#define Dn 81
#define TH 4
#define TW 64
#define CC 4
#define NCH (Cn / CC)       // 32 chunks
#define S2H (TH + 8)        // 12
#define S2W (TW + 8)        // 72
#define NTHR 192

#define S1_F4 (CC * TH * TW / 4)    // 256
#define S2_F4 (CC * S2H * S2W / 4)  // 864

typedef unsigned long long ull;

__device__ __forceinline__ ull fma2(ull a, ull b, ull c) {
    ull d;
    asm("fma.rn.f32x2 %0, %1, %2, %3;" : "=l"(d) : "l"(a), "l"(b), "l"(c));
    return d;
}
__device__ __forceinline__ ull pack2(float lo, float hi) {
    ull d;
    asm("mov.b64 %0, {%1, %2};" : "=l"(d) : "f"(lo), "f"(hi));
    return d;
}
__device__ __forceinline__ float2 unpack2(ull s) {
    float lo, hi;
    asm("mov.b64 {%0, %1}, %2;" : "=f"(lo), "=f"(hi) : "l"(s));
    return make_float2(lo, hi);
}

__device__ __forceinline__ void cp16(uint32_t saddr, const float* gptr, bool ok) {
    int sz = ok ? 16 : 0;
    asm volatile("cp.async.cg.shared.global [%0], [%1], 16, %2;\n"
                 :: "r"(saddr), "l"(gptr), "r"(sz));
}
__device__ __forceinline__ void cp_commit() {
    asm volatile("cp.async.commit_group;\n" ::: "memory");
}
template <int N>
__device__ __forceinline__ void cp_wait() {
    asm volatile("cp.async.wait_group %0;\n" :: "n"(N) : "memory");
}

__global__ __launch_bounds__(NTHR, 2)
void costvol_kernel(const float* __restrict__ x1,
                    const float* __restrict__ x2,
                    float* __restrict__ out) {
    __shared__ __align__(16) float s1[2][CC][TH][TW];   // 2 * 4 KB
    __shared__ __align__(16) float s2[2][CC][S2H][S2W]; // 2 * 13.5 KB

    const int w0 = blockIdx.x * TW;
    const int h0 = blockIdx.y * TH;
    const int b  = blockIdx.z;

    const int tid = threadIdx.x;
    const int g   = tid / 64;        // i-group 0..2
    const int r   = tid - g * 64;
    const int tx  = r & 15;          // 16 pixel-quads across w
    const int ty  = r >> 4;          // 4 rows

    const float* x1b = x1 + (size_t)(b * Cn) * Hn * Wn;
    const float* x2b = x2 + (size_t)(b * Cn) * Hn * Wn;

    auto prefetch = [&](int c0, int st) {
        // s1: 256 float4
#pragma unroll
        for (int q = 0; q < 2; q++) {
            int f = tid + q * NTHR;
            if (f < S1_F4) {
                int cc  = f >> 6;
                int rem = f & 63;
                int hh  = rem >> 4;
                int k4  = rem & 15;
                uint32_t sa = (uint32_t)__cvta_generic_to_shared(&s1[st][cc][hh][4 * k4]);
                cp16(sa, x1b + (((size_t)(c0 + cc) * Hn + h0 + hh) * Wn + w0 + 4 * k4), true);
            }
        }
        // s2: 864 float4
#pragma unroll
        for (int q = 0; q < 5; q++) {
            int f = tid + q * NTHR;
            if (f < S2_F4) {
                int cc  = f / (S2H * (S2W / 4));
                int rem = f - cc * (S2H * (S2W / 4));
                int row = rem / (S2W / 4);
                int k4  = rem - row * (S2W / 4);
                int hg  = h0 - 4 + row;
                int wg  = w0 - 4 + 4 * k4;
                bool ok = ((unsigned)hg < (unsigned)Hn) && ((unsigned)wg < (unsigned)Wn);
                const float* gp = ok ? (x2b + (((size_t)cc + c0) * Hn + hg) * (size_t)Wn + wg)
                                     : x2b;
                uint32_t sa = (uint32_t)__cvta_generic_to_shared(&s2[st][cc][row][4 * k4]);
                cp16(sa, gp, ok);
            }
        }
        cp_commit();
    };

    // acc[u][jj][half]: half0 = px(0,1), half1 = px(2,3); 0ull == (0.f, 0.f)
    ull acc[3][9][2];
#pragma unroll
    for (int u = 0; u < 3; u++)
#pragma unroll
        for (int jj = 0; jj < 9; jj++) { acc[u][jj][0] = 0ull; acc[u][jj][1] = 0ull; }

    prefetch(0, 0);

    for (int it = 0; it < NCH; it++) {
        const int st = it & 1;
        if (it + 1 < NCH) {
            prefetch((it + 1) * CC, st ^ 1);
            cp_wait<1>();
        } else {
            cp_wait<0>();
        }
        __syncthreads();

#pragma unroll
        for (int cc = 0; cc < CC; cc++) {
            const float4 av = *(const float4*)&s1[st][cc][ty][4 * tx];
            const ull A01 = pack2(av.x, av.y);
            const ull A23 = pack2(av.z, av.w);
#pragma unroll
            for (int u = 0; u < 3; u++) {
                const float* rp = &s2[st][cc][ty + 8 - 3 * g - u][4 * tx];
                const float4 q0 = *(const float4*)(rp);
                const float4 q1 = *(const float4*)(rp + 4);
                const float4 q2 = *(const float4*)(rp + 8);
                const float w[12] = {q0.x, q0.y, q0.z, q0.w,
                                     q1.x, q1.y, q1.z, q1.w,
                                     q2.x, q2.y, q2.z, q2.w};
                // P[m] = (w[m], w[m+1]), m = 0..10
                ull P[11];
#pragma unroll
                for (int m = 0; m < 11; m++) P[m] = pack2(w[m], w[m + 1]);
#pragma unroll
                for (int jj = 0; jj < 9; jj++) {
                    acc[u][jj][0] = fma2(A01, P[8 - jj], acc[u][jj][0]);   // px 0,1
                    acc[u][jj][1] = fma2(A23, P[10 - jj], acc[u][jj][1]);  // px 2,3
                }
            }
        }
        __syncthreads();
    }

    // ---- epilogue: k = (9*ii + jj + 41) mod 81, ii = 3g+u ----
    const float inv = 1.0f / 81.0f;
    const int hg = h0 + ty;
    const int wg = w0 + 4 * tx;
#pragma unroll
    for (int u = 0; u < 3; u++) {
        const int ii = 3 * g + u;
#pragma unroll
        for (int jj = 0; jj < 9; jj++) {
            int k = 9 * ii + jj + 41;
            if (k >= 81) k -= 81;
            const float2 p0 = unpack2(acc[u][jj][0]);
            const float2 p1 = unpack2(acc[u][jj][1]);
            float4 v = make_float4(p0.x * inv, p0.y * inv, p1.x * inv, p1.y * inv);
            *(float4*)(out + (((size_t)((b * Dn + k) * Hn + hg)) * Wn + wg)) = v;
        }
    }
}

extern "C" void kernel_launch(void* const* d_in, const int* in_sizes, int n_in,
                              void* d_out, int out_size) {
    (void)in_sizes; (void)n_in; (void)out_size;
    const float* x1 = (const float*)d_in[0];
    const float* x2 = (const float*)d_in[1];
    float* out = (float*)d_out;
    dim3 grid(Wn / TW, Hn / TH, Bn);   // (4, 32, 4) = 512 blocks
    costvol_kernel<<<grid, NTHR>>>(x1, x2, out);
}

// round 10
// speedup vs baseline: 1.9143x; 1.3621x over previous
#include <cuda_runtime.h>
#include <cstdint>

// Cost volume: out[b,k,h,w] = (1/81) * sum_c x1[b,c,h,w] * x2[b,c,h-i,w-j]
//   i,j in [-4,4], k = (9i+j) mod 81. Zero padding. B=4,C=128,H=128,W=256,D=81.
//
// R9 = R2 (best: 94.6us, 89% of the scalar FFMA rt=2 wall) with the per-chunk
// barrier count halved: pipeline reordered to wait -> barrier -> prefetch(next
// stage) -> compute. The single barrier both publishes chunk `it` and proves
// all readers of stage st^1 finished, so refilling st^1 needs no 2nd barrier.
// Geometry unchanged: 192 thr = 3 groups x 64; group g owns di in {3g..3g+2};
// 4h x 64w tile, P=4 px/thread; CC=4 cp.async double buffer; lb(192,2).
// (FFMA2 path measured dead in R8: no throughput gain + pack-MOV overhead.)

#define Bn 4
#define Cn 128
#define Hn 128
#define Wn 256
#define Dn 81
#define TH 4
#define TW 64
#define CC 4
#define NCH (Cn / CC)       // 32 chunks
#define S2H (TH + 8)        // 12
#define S2W (TW + 8)        // 72
#define NTHR 192

#define S1_F4 (CC * TH * TW / 4)    // 256
#define S2_F4 (CC * S2H * S2W / 4)  // 864

__device__ __forceinline__ void cp16(uint32_t saddr, const float* gptr, bool ok) {
    int sz = ok ? 16 : 0;
    asm volatile("cp.async.cg.shared.global [%0], [%1], 16, %2;\n"
                 :: "r"(saddr), "l"(gptr), "r"(sz));
}
__device__ __forceinline__ void cp_commit() {
    asm volatile("cp.async.commit_group;\n" ::: "memory");
}
template <int N>
__device__ __forceinline__ void cp_wait() {
    asm volatile("cp.async.wait_group %0;\n" :: "n"(N) : "memory");
}

__global__ __launch_bounds__(NTHR, 2)
void costvol_kernel(const float* __restrict__ x1,
                    const float* __restrict__ x2,
                    float* __restrict__ out) {
    __shared__ __align__(16) float s1[2][CC][TH][TW];   // 2 * 4 KB
    __shared__ __align__(16) float s2[2][CC][S2H][S2W]; // 2 * 13.5 KB

    const int w0 = blockIdx.x * TW;
    const int h0 = blockIdx.y * TH;
    const int b  = blockIdx.z;

    const int tid = threadIdx.x;
    const int g   = tid / 64;        // i-group 0..2
    const int r   = tid - g * 64;
    const int tx  = r & 15;          // 16 pixel-quads across w
    const int ty  = r >> 4;          // 4 rows

    const float* x1b = x1 + (size_t)(b * Cn) * Hn * Wn;
    const float* x2b = x2 + (size_t)(b * Cn) * Hn * Wn;

    auto prefetch = [&](int c0, int st) {
        // s1: 256 float4
#pragma unroll
        for (int q = 0; q < 2; q++) {
            int f = tid + q * NTHR;
            if (f < S1_F4) {
                int cc  = f >> 6;
                int rem = f & 63;
                int hh  = rem >> 4;
                int k4  = rem & 15;
                uint32_t sa = (uint32_t)__cvta_generic_to_shared(&s1[st][cc][hh][4 * k4]);
                cp16(sa, x1b + (((size_t)(c0 + cc) * Hn + h0 + hh) * Wn + w0 + 4 * k4), true);
            }
        }
        // s2: 864 float4
#pragma unroll
        for (int q = 0; q < 5; q++) {
            int f = tid + q * NTHR;
            if (f < S2_F4) {
                int cc  = f / (S2H * (S2W / 4));
                int rem = f - cc * (S2H * (S2W / 4));
                int row = rem / (S2W / 4);
                int k4  = rem - row * (S2W / 4);
                int hg  = h0 - 4 + row;
                int wg  = w0 - 4 + 4 * k4;
                bool ok = ((unsigned)hg < (unsigned)Hn) && ((unsigned)wg < (unsigned)Wn);
                const float* gp = ok ? (x2b + (((size_t)cc + c0) * Hn + hg) * (size_t)Wn + wg)
                                     : x2b;
                uint32_t sa = (uint32_t)__cvta_generic_to_shared(&s2[st][cc][row][4 * k4]);
                cp16(sa, gp, ok);
            }
        }
        cp_commit();
    };

    float acc[3][9][4];
#pragma unroll
    for (int u = 0; u < 3; u++)
#pragma unroll
        for (int jj = 0; jj < 9; jj++)
#pragma unroll
            for (int p = 0; p < 4; p++) acc[u][jj][p] = 0.f;

    prefetch(0, 0);

    for (int it = 0; it < NCH; it++) {
        const int st = it & 1;
        // Chunk `it` was committed in the previous iteration (or before the
        // loop); no other group is outstanding, so wait for full drain.
        cp_wait<0>();
        // Single barrier: publishes chunk `it` to all threads AND proves every
        // thread finished reading stage st^1 (chunk it-1), so refilling st^1
        // below is race-free.
        __syncthreads();
        if (it + 1 < NCH) prefetch((it + 1) * CC, st ^ 1);

#pragma unroll
        for (int cc = 0; cc < CC; cc++) {
            const float4 av = *(const float4*)&s1[st][cc][ty][4 * tx];
            const float a[4] = {av.x, av.y, av.z, av.w};
#pragma unroll
            for (int u = 0; u < 3; u++) {
                const float* rp = &s2[st][cc][ty + 8 - 3 * g - u][4 * tx];
                float wnd[12];
#pragma unroll
                for (int m = 0; m < 12; m += 4) {
                    float4 t = *(const float4*)(rp + m);   // aligned LDS.128
                    wnd[m] = t.x; wnd[m + 1] = t.y; wnd[m + 2] = t.z; wnd[m + 3] = t.w;
                }
#pragma unroll
                for (int jj = 0; jj < 9; jj++) {
#pragma unroll
                    for (int p = 0; p < 4; p++)
                        acc[u][jj][p] += a[p] * wnd[p + 8 - jj];
                }
            }
        }
    }

    // ---- epilogue: k = (9*ii + jj + 41) mod 81, ii = 3g+u ----
    const float inv = 1.0f / 81.0f;
    const int hg = h0 + ty;
    const int wg = w0 + 4 * tx;
#pragma unroll
    for (int u = 0; u < 3; u++) {
        const int ii = 3 * g + u;
#pragma unroll
        for (int jj = 0; jj < 9; jj++) {
            int k = 9 * ii + jj + 41;
            if (k >= 81) k -= 81;
            float4 v = make_float4(acc[u][jj][0] * inv, acc[u][jj][1] * inv,
                                   acc[u][jj][2] * inv, acc[u][jj][3] * inv);
            *(float4*)(out + (((size_t)((b * Dn + k) * Hn + hg)) * Wn + wg)) = v;
        }
    }
}

extern "C" void kernel_launch(void* const* d_in, const int* in_sizes, int n_in,
                              void* d_out, int out_size) {
    (void)in_sizes; (void)n_in; (void)out_size;
    const float* x1 = (const float*)d_in[0];
    const float* x2 = (const float*)d_in[1];
    float* out = (float*)d_out;
    dim3 grid(Wn / TW, Hn / TH, Bn);   // (4, 32, 4) = 512 blocks
    costvol_kernel<<<grid, NTHR>>>(x1, x2, out);
}